// round 2
// baseline (speedup 1.0000x reference)
#include <cuda_runtime.h>
#include <math.h>

#define BB 2
#define SQ 2048
#define SKV 4096
#define DM 1024
#define NH 16
#define DK 64

// ---------------- scratch (device globals; no allocation allowed) ----------------
__device__ float g_normed[(size_t)BB * SQ * DM];   // 16 MB
__device__ float g_q[(size_t)BB * SQ * DM];        // 16 MB
__device__ float g_k[(size_t)BB * SKV * DM];       // 32 MB
__device__ float g_v[(size_t)BB * SKV * DM];       // 32 MB
__device__ float g_ctx[(size_t)BB * SQ * DM];      // 16 MB

// ---------------- RMSNorm (T5: no mean subtraction) ----------------
__global__ void rmsnorm_kernel(const float* __restrict__ x, const float* __restrict__ w) {
    int row = blockIdx.x;
    const float* xr = x + (size_t)row * DM;
    int i = threadIdx.x * 4;
    float4 xv = *(const float4*)(xr + i);
    float s = xv.x * xv.x + xv.y * xv.y + xv.z * xv.z + xv.w * xv.w;
#pragma unroll
    for (int off = 16; off > 0; off >>= 1) s += __shfl_xor_sync(0xffffffffu, s, off);
    __shared__ float red[8];
    int wid = threadIdx.x >> 5, lane = threadIdx.x & 31;
    if (lane == 0) red[wid] = s;
    __syncthreads();
    float tot = 0.f;
#pragma unroll
    for (int k = 0; k < 8; k++) tot += red[k];
    float inv = rsqrtf(tot * (1.0f / DM) + 1e-6f);
    float4 wv = *(const float4*)(w + i);
    float4 yv = make_float4(wv.x * xv.x * inv, wv.y * xv.y * inv,
                            wv.z * xv.z * inv, wv.w * xv.w * inv);
    *(float4*)&g_normed[(size_t)row * DM + i] = yv;
}

// ---------------- SGEMM: C[M,N] = A[M,K] @ B[K,N] (+ optional residual) ----------------
#define BM 128
#define BN 128
#define BK 8

template <bool RES>
__global__ void sgemm_kernel(const float* __restrict__ A, const float* __restrict__ Bm,
                             const float* __restrict__ Res, float* __restrict__ C,
                             int M, int N, int K) {
    __shared__ float As[2][BK][BM];
    __shared__ float Bs[2][BK][BN];
    int tid = threadIdx.x;
    int m0 = blockIdx.y * BM, n0 = blockIdx.x * BN;
    int tx = tid % 16, ty = tid / 16;

    int arow = tid >> 1;             // 0..127
    int acol = (tid & 1) * 4;        // 0 or 4
    int brow = tid >> 5;             // 0..7
    int bcol = (tid & 31) * 4;       // 0..124

    const float* Aptr = A + (size_t)(m0 + arow) * K + acol;
    const float* Bptr = Bm + (size_t)brow * N + n0 + bcol;

    float acc[8][8];
#pragma unroll
    for (int i = 0; i < 8; i++)
#pragma unroll
        for (int j = 0; j < 8; j++) acc[i][j] = 0.f;

    float4 a_reg = *(const float4*)Aptr;
    float4 b_reg = *(const float4*)Bptr;
    As[0][acol + 0][arow] = a_reg.x;
    As[0][acol + 1][arow] = a_reg.y;
    As[0][acol + 2][arow] = a_reg.z;
    As[0][acol + 3][arow] = a_reg.w;
    *(float4*)&Bs[0][brow][bcol] = b_reg;
    __syncthreads();

    int nt = K / BK;
    for (int kt = 0; kt < nt; kt++) {
        int cur = kt & 1, nxt = cur ^ 1;
        if (kt + 1 < nt) {
            a_reg = *(const float4*)(Aptr + (kt + 1) * BK);
            b_reg = *(const float4*)(Bptr + (size_t)(kt + 1) * BK * N);
        }
#pragma unroll
        for (int kk = 0; kk < BK; kk++) {
            float4 a0 = *(float4*)&As[cur][kk][ty * 8];
            float4 a1 = *(float4*)&As[cur][kk][ty * 8 + 4];
            float4 b0 = *(float4*)&Bs[cur][kk][tx * 8];
            float4 b1 = *(float4*)&Bs[cur][kk][tx * 8 + 4];
            float af[8] = {a0.x, a0.y, a0.z, a0.w, a1.x, a1.y, a1.z, a1.w};
            float bf[8] = {b0.x, b0.y, b0.z, b0.w, b1.x, b1.y, b1.z, b1.w};
#pragma unroll
            for (int i = 0; i < 8; i++)
#pragma unroll
                for (int j = 0; j < 8; j++) acc[i][j] = fmaf(af[i], bf[j], acc[i][j]);
        }
        if (kt + 1 < nt) {
            As[nxt][acol + 0][arow] = a_reg.x;
            As[nxt][acol + 1][arow] = a_reg.y;
            As[nxt][acol + 2][arow] = a_reg.z;
            As[nxt][acol + 3][arow] = a_reg.w;
            *(float4*)&Bs[nxt][brow][bcol] = b_reg;
            __syncthreads();
        }
    }

#pragma unroll
    for (int i = 0; i < 8; i++) {
        size_t row = (size_t)(m0 + ty * 8 + i);
#pragma unroll
        for (int j4 = 0; j4 < 8; j4 += 4) {
            size_t idx = row * N + n0 + tx * 8 + j4;
            float4 v = make_float4(acc[i][j4 + 0], acc[i][j4 + 1], acc[i][j4 + 2], acc[i][j4 + 3]);
            if (RES) {
                float4 r = *(const float4*)&Res[idx];
                v.x += r.x; v.y += r.y; v.z += r.z; v.w += r.w;
            }
            *(float4*)&C[idx] = v;
        }
    }
}

// ---------------- Flash attention (fp32, no 1/sqrt(d) scaling) ----------------
// Grid: (SQ/64, NH, BB), 256 threads. smem: Qs, Ks(/Ps), Vs each [64][68].
#define LDP 68

__global__ void attn_kernel(const float* __restrict__ mask) {
    extern __shared__ float sm[];
    float* Qs = sm;                 // [64][LDP]
    float* Ks = sm + 64 * LDP;      // reused as P after S-compute
    float* Vs = sm + 2 * 64 * LDP;

    int b = blockIdx.z, h = blockIdx.y;
    int q0 = blockIdx.x * 64;
    int tid = threadIdx.x;
    int tc = tid % 16, tr = tid / 16;

    const float* qbase = g_q + ((size_t)(b * SQ + q0)) * DM + h * DK;
    const float* kbase = g_k + ((size_t)b * SKV) * DM + h * DK;
    const float* vbase = g_v + ((size_t)b * SKV) * DM + h * DK;
    const float* mrow = mask + (size_t)b * SKV;

    // load Q tile (64 x 64)
    for (int t = tid; t < 64 * 16; t += 256) {
        int r = t >> 4, c4 = (t & 15) * 4;
        *(float4*)&Qs[r * LDP + c4] = *(const float4*)(qbase + (size_t)r * DM + c4);
    }

    float m_i[4], l_i[4], o[4][4];
#pragma unroll
    for (int i = 0; i < 4; i++) {
        m_i[i] = -1e30f;
        l_i[i] = 0.f;
#pragma unroll
        for (int j = 0; j < 4; j++) o[i][j] = 0.f;
    }

    for (int jt = 0; jt < SKV / 64; jt++) {
        __syncthreads();  // prior O-update reads of Ks/Vs complete
        for (int t = tid; t < 64 * 16; t += 256) {
            int r = t >> 4, c4 = (t & 15) * 4;
            *(float4*)&Ks[r * LDP + c4] = *(const float4*)(kbase + (size_t)(jt * 64 + r) * DM + c4);
            *(float4*)&Vs[r * LDP + c4] = *(const float4*)(vbase + (size_t)(jt * 64 + r) * DM + c4);
        }
        __syncthreads();

        // S = Q K^T  (+ mask per kv column)
        float s[4][4];
#pragma unroll
        for (int j = 0; j < 4; j++) {
            float mv = mrow[jt * 64 + tc * 4 + j];
#pragma unroll
            for (int i = 0; i < 4; i++) s[i][j] = mv;
        }
        for (int kk = 0; kk < 64; kk += 4) {
            float4 q4[4], k4[4];
#pragma unroll
            for (int i = 0; i < 4; i++) q4[i] = *(float4*)&Qs[(tr * 4 + i) * LDP + kk];
#pragma unroll
            for (int j = 0; j < 4; j++) k4[j] = *(float4*)&Ks[(tc * 4 + j) * LDP + kk];
#pragma unroll
            for (int i = 0; i < 4; i++)
#pragma unroll
                for (int j = 0; j < 4; j++) {
                    s[i][j] = fmaf(q4[i].x, k4[j].x, s[i][j]);
                    s[i][j] = fmaf(q4[i].y, k4[j].y, s[i][j]);
                    s[i][j] = fmaf(q4[i].z, k4[j].z, s[i][j]);
                    s[i][j] = fmaf(q4[i].w, k4[j].w, s[i][j]);
                }
        }

        // online softmax update (row groups = 16 lanes sharing tr)
#pragma unroll
        for (int i = 0; i < 4; i++) {
            float rmax = fmaxf(fmaxf(s[i][0], s[i][1]), fmaxf(s[i][2], s[i][3]));
#pragma unroll
            for (int off = 8; off > 0; off >>= 1)
                rmax = fmaxf(rmax, __shfl_xor_sync(0xffffffffu, rmax, off));
            float mnew = fmaxf(m_i[i], rmax);
            float scale = __expf(m_i[i] - mnew);
            float rsum = 0.f;
#pragma unroll
            for (int j = 0; j < 4; j++) {
                float p = __expf(s[i][j] - mnew);
                s[i][j] = p;
                rsum += p;
            }
#pragma unroll
            for (int off = 8; off > 0; off >>= 1)
                rsum += __shfl_xor_sync(0xffffffffu, rsum, off);
            l_i[i] = l_i[i] * scale + rsum;
            m_i[i] = mnew;
#pragma unroll
            for (int j = 0; j < 4; j++) o[i][j] *= scale;
        }

        __syncthreads();  // all S reads of Ks done before overwrite with P
#pragma unroll
        for (int i = 0; i < 4; i++)
            *(float4*)&Ks[(tr * 4 + i) * LDP + tc * 4] =
                make_float4(s[i][0], s[i][1], s[i][2], s[i][3]);
        __syncthreads();

        // O += P @ V
        for (int kk = 0; kk < 64; kk++) {
            float4 v4 = *(float4*)&Vs[kk * LDP + tc * 4];
#pragma unroll
            for (int i = 0; i < 4; i++) {
                float p = Ks[(tr * 4 + i) * LDP + kk];
                o[i][0] = fmaf(p, v4.x, o[i][0]);
                o[i][1] = fmaf(p, v4.y, o[i][1]);
                o[i][2] = fmaf(p, v4.z, o[i][2]);
                o[i][3] = fmaf(p, v4.w, o[i][3]);
            }
        }
    }

    float* cbase = g_ctx + ((size_t)(b * SQ + q0)) * DM + h * DK;
#pragma unroll
    for (int i = 0; i < 4; i++) {
        float inv = 1.0f / l_i[i];
        *(float4*)&cbase[(size_t)(tr * 4 + i) * DM + tc * 4] =
            make_float4(o[i][0] * inv, o[i][1] * inv, o[i][2] * inv, o[i][3] * inv);
    }
}

// ---------------- launch ----------------
extern "C" void kernel_launch(void* const* d_in, const int* in_sizes, int n_in,
                              void* d_out, int out_size) {
    const float* hidden = (const float*)d_in[0];
    const float* kv     = (const float*)d_in[1];
    const float* mask   = (const float*)d_in[2];
    const float* lnw    = (const float*)d_in[3];
    const float* Wq     = (const float*)d_in[4];
    const float* Wk     = (const float*)d_in[5];
    const float* Wv     = (const float*)d_in[6];
    const float* Wo     = (const float*)d_in[7];
    float* out = (float*)d_out;

    float *p_normed, *p_q, *p_k, *p_v, *p_ctx;
    cudaGetSymbolAddress((void**)&p_normed, g_normed);
    cudaGetSymbolAddress((void**)&p_q, g_q);
    cudaGetSymbolAddress((void**)&p_k, g_k);
    cudaGetSymbolAddress((void**)&p_v, g_v);
    cudaGetSymbolAddress((void**)&p_ctx, g_ctx);

    // 1. RMSNorm
    rmsnorm_kernel<<<BB * SQ, 256>>>(hidden, lnw);

    // 2. projections
    dim3 gq(DM / BN, (BB * SQ) / BM);
    dim3 gkv(DM / BN, (BB * SKV) / BM);
    sgemm_kernel<false><<<gq, 256>>>(p_normed, Wq, nullptr, p_q, BB * SQ, DM, DM);
    sgemm_kernel<false><<<gkv, 256>>>(kv, Wk, nullptr, p_k, BB * SKV, DM, DM);
    sgemm_kernel<false><<<gkv, 256>>>(kv, Wv, nullptr, p_v, BB * SKV, DM, DM);

    // 3. flash attention
    const int ATTN_SMEM = 3 * 64 * LDP * sizeof(float);
    cudaFuncSetAttribute(attn_kernel, cudaFuncAttributeMaxDynamicSharedMemorySize, ATTN_SMEM);
    dim3 ga(SQ / 64, NH, BB);
    attn_kernel<<<ga, 256, ATTN_SMEM>>>(mask);

    // 4. output projection + residual
    sgemm_kernel<true><<<gq, 256>>>(p_ctx, Wo, hidden, out, BB * SQ, DM, DM);
}

// round 3
// speedup vs baseline: 2.7846x; 2.7846x over previous
#include <cuda_runtime.h>
#include <math.h>
#include <stdint.h>

#define BB 2
#define SQ 2048
#define SKV 4096
#define DM 1024
#define NH 16
#define DK 64

// ---------------- scratch (device globals; no allocation allowed) ----------------
__device__ float g_normed[(size_t)BB * SQ * DM];   // 16 MB
__device__ float g_q[(size_t)BB * SQ * DM];        // 16 MB
__device__ float g_k[(size_t)BB * SKV * DM];       // 32 MB
__device__ float g_v[(size_t)BB * SKV * DM];       // 32 MB
__device__ float g_ctx[(size_t)BB * SQ * DM];      // 16 MB

// ---------------- helpers ----------------
__device__ __forceinline__ uint32_t f2tf32(float x) {
    uint32_t u;
    asm("cvt.rna.tf32.f32 %0, %1;" : "=r"(u) : "f"(x));
    return u;
}

// D = A@B + C (in place on c). A row-major frag, B col-major frag, fp32 accum.
__device__ __forceinline__ void mma_tf32(float* c, const uint32_t* a, const uint32_t* b) {
    asm volatile(
        "mma.sync.aligned.m16n8k8.row.col.f32.tf32.tf32.f32 "
        "{%0,%1,%2,%3}, {%4,%5,%6,%7}, {%8,%9}, {%0,%1,%2,%3};"
        : "+f"(c[0]), "+f"(c[1]), "+f"(c[2]), "+f"(c[3])
        : "r"(a[0]), "r"(a[1]), "r"(a[2]), "r"(a[3]), "r"(b[0]), "r"(b[1]));
}

// ---------------- RMSNorm (T5: no mean subtraction) ----------------
__global__ void rmsnorm_kernel(const float* __restrict__ x, const float* __restrict__ w) {
    int row = blockIdx.x;
    const float* xr = x + (size_t)row * DM;
    int i = threadIdx.x * 4;
    float4 xv = *(const float4*)(xr + i);
    float s = xv.x * xv.x + xv.y * xv.y + xv.z * xv.z + xv.w * xv.w;
#pragma unroll
    for (int off = 16; off > 0; off >>= 1) s += __shfl_xor_sync(0xffffffffu, s, off);
    __shared__ float red[8];
    int wid = threadIdx.x >> 5, lane = threadIdx.x & 31;
    if (lane == 0) red[wid] = s;
    __syncthreads();
    float tot = 0.f;
#pragma unroll
    for (int k = 0; k < 8; k++) tot += red[k];
    float inv = rsqrtf(tot * (1.0f / DM) + 1e-6f);
    float4 wv = *(const float4*)(w + i);
    float4 yv = make_float4(wv.x * xv.x * inv, wv.y * xv.y * inv,
                            wv.z * xv.z * inv, wv.w * xv.w * inv);
    *(float4*)&g_normed[(size_t)row * DM + i] = yv;
}

// ---------------- tf32 GEMM: C[M,N] = A[M,K] @ B[K,N] (+ optional residual) ----------------
// 128 threads (4 warps 2x2, each 64x64), tile 128x128x16, double-buffered.
#define GBK 16
#define LDA 140   // As[k][m] pad: banks (12*tig + g) distinct
#define LDB 136   // Bs[k][n] pad: banks (8*tig + g) distinct

template <bool RES>
__global__ __launch_bounds__(128) void tf32_gemm(const float* __restrict__ A,
                                                 const float* __restrict__ B,
                                                 const float* __restrict__ Res,
                                                 float* __restrict__ C,
                                                 int M, int N, int K) {
    __shared__ uint32_t As[2][GBK][LDA];
    __shared__ uint32_t Bs[2][GBK][LDB];
    int tid = threadIdx.x;
    int wid = tid >> 5, lane = tid & 31;
    int g = lane >> 2, tig = lane & 3;
    int warp_m = (wid >> 1) * 64, warp_n = (wid & 1) * 64;
    int m0 = blockIdx.y * 128, n0 = blockIdx.x * 128;

    float acc[4][8][4];
#pragma unroll
    for (int mt = 0; mt < 4; mt++)
#pragma unroll
        for (int nt = 0; nt < 8; nt++)
#pragma unroll
            for (int e = 0; e < 4; e++) acc[mt][nt][e] = 0.f;

    const float* ap = A + (size_t)(m0 + tid) * K;
    float4 pa[4], pb[4];

    // prefetch tile 0
#pragma unroll
    for (int i = 0; i < 4; i++) pa[i] = *(const float4*)(ap + i * 4);
#pragma unroll
    for (int i = 0; i < 4; i++) {
        int idx = tid + 128 * i;
        int r = idx >> 5, c4 = (idx & 31) * 4;
        pb[i] = *(const float4*)(B + (size_t)r * N + n0 + c4);
    }
    // store tile 0
#pragma unroll
    for (int i = 0; i < 4; i++) {
        As[0][i * 4 + 0][tid] = f2tf32(pa[i].x);
        As[0][i * 4 + 1][tid] = f2tf32(pa[i].y);
        As[0][i * 4 + 2][tid] = f2tf32(pa[i].z);
        As[0][i * 4 + 3][tid] = f2tf32(pa[i].w);
    }
#pragma unroll
    for (int i = 0; i < 4; i++) {
        int idx = tid + 128 * i;
        int r = idx >> 5, c4 = (idx & 31) * 4;
        uint4 u = make_uint4(f2tf32(pb[i].x), f2tf32(pb[i].y), f2tf32(pb[i].z), f2tf32(pb[i].w));
        *(uint4*)&Bs[0][r][c4] = u;
    }
    __syncthreads();

    int nt_tiles = K / GBK;
    for (int kt = 0; kt < nt_tiles; kt++) {
        int buf = kt & 1;
        if (kt + 1 < nt_tiles) {
            int k0 = (kt + 1) * GBK;
#pragma unroll
            for (int i = 0; i < 4; i++) pa[i] = *(const float4*)(ap + k0 + i * 4);
#pragma unroll
            for (int i = 0; i < 4; i++) {
                int idx = tid + 128 * i;
                int r = idx >> 5, c4 = (idx & 31) * 4;
                pb[i] = *(const float4*)(B + (size_t)(k0 + r) * N + n0 + c4);
            }
        }
        // compute on buf
#pragma unroll
        for (int ks = 0; ks < 2; ks++) {
            int kb = ks * 8;
            uint32_t af[4][4], bf[8][2];
#pragma unroll
            for (int mt = 0; mt < 4; mt++) {
                int mm = warp_m + mt * 16 + g;
                af[mt][0] = As[buf][kb + tig][mm];
                af[mt][1] = As[buf][kb + tig][mm + 8];
                af[mt][2] = As[buf][kb + tig + 4][mm];
                af[mt][3] = As[buf][kb + tig + 4][mm + 8];
            }
#pragma unroll
            for (int ntl = 0; ntl < 8; ntl++) {
                int nn = warp_n + ntl * 8 + g;
                bf[ntl][0] = Bs[buf][kb + tig][nn];
                bf[ntl][1] = Bs[buf][kb + tig + 4][nn];
            }
#pragma unroll
            for (int mt = 0; mt < 4; mt++)
#pragma unroll
                for (int ntl = 0; ntl < 8; ntl++) mma_tf32(acc[mt][ntl], af[mt], bf[ntl]);
        }
        if (kt + 1 < nt_tiles) {
            int nb = buf ^ 1;
#pragma unroll
            for (int i = 0; i < 4; i++) {
                As[nb][i * 4 + 0][tid] = f2tf32(pa[i].x);
                As[nb][i * 4 + 1][tid] = f2tf32(pa[i].y);
                As[nb][i * 4 + 2][tid] = f2tf32(pa[i].z);
                As[nb][i * 4 + 3][tid] = f2tf32(pa[i].w);
            }
#pragma unroll
            for (int i = 0; i < 4; i++) {
                int idx = tid + 128 * i;
                int r = idx >> 5, c4 = (idx & 31) * 4;
                uint4 u = make_uint4(f2tf32(pb[i].x), f2tf32(pb[i].y), f2tf32(pb[i].z), f2tf32(pb[i].w));
                *(uint4*)&Bs[nb][r][c4] = u;
            }
            __syncthreads();
        }
    }

    // epilogue
#pragma unroll
    for (int mt = 0; mt < 4; mt++) {
#pragma unroll
        for (int ntl = 0; ntl < 8; ntl++) {
            int row = m0 + warp_m + mt * 16 + g;
            int col = n0 + warp_n + ntl * 8 + 2 * tig;
            size_t i0 = (size_t)row * N + col;
            size_t i1 = (size_t)(row + 8) * N + col;
            float2 v0 = make_float2(acc[mt][ntl][0], acc[mt][ntl][1]);
            float2 v1 = make_float2(acc[mt][ntl][2], acc[mt][ntl][3]);
            if (RES) {
                float2 r0 = *(const float2*)&Res[i0];
                float2 r1 = *(const float2*)&Res[i1];
                v0.x += r0.x; v0.y += r0.y;
                v1.x += r1.x; v1.y += r1.y;
            }
            *(float2*)&C[i0] = v0;
            *(float2*)&C[i1] = v1;
        }
    }
}

// ---------------- Flash attention, tf32 mma ----------------
// CTA: 256 thr (8 warps), q-tile 128 (warp w -> rows 16w..16w+16), kv-tile 64.
// smem (uint32 tf32): Qs[64][140] ([d][q]), Ks[64][72] ([d][kv]),
//                     Vs[64][72] ([kv][d]), Ps[64][140] ([kv][q])
#define ALDQ 140
#define ALDK 72
#define ATTN_SMEM_U32 (64 * ALDQ * 2 + 64 * ALDK * 2)

__global__ __launch_bounds__(256) void attn_tf32(const float* __restrict__ mask) {
    extern __shared__ uint32_t sm[];
    uint32_t* Qs = sm;                       // 64*140
    uint32_t* Ks = Qs + 64 * ALDQ;           // 64*72
    uint32_t* Vs = Ks + 64 * ALDK;           // 64*72
    uint32_t* Ps = Vs + 64 * ALDK;           // 64*140

    int b = blockIdx.z, h = blockIdx.y;
    int q0 = blockIdx.x * 128;
    int tid = threadIdx.x;
    int wid = tid >> 5, lane = tid & 31;
    int g = lane >> 2, tig = lane & 3;
    int mbase = wid * 16;

    const float* mrow = mask + (size_t)b * SKV;

    // stage Q: Qs[d][q] = Q[q][d]
    {
        int qrow = tid & 127, half = tid >> 7;
        const float* qp = g_q + (size_t)(b * SQ + q0 + qrow) * DM + h * DK + half * 32;
#pragma unroll
        for (int i = 0; i < 8; i++) {
            float4 v = *(const float4*)(qp + i * 4);
            int d0 = half * 32 + i * 4;
            Qs[(d0 + 0) * ALDQ + qrow] = f2tf32(v.x);
            Qs[(d0 + 1) * ALDQ + qrow] = f2tf32(v.y);
            Qs[(d0 + 2) * ALDQ + qrow] = f2tf32(v.z);
            Qs[(d0 + 3) * ALDQ + qrow] = f2tf32(v.w);
        }
    }

    float m0s = -1e30f, m1s = -1e30f, l0 = 0.f, l1 = 0.f;
    float oacc[8][4];
#pragma unroll
    for (int d = 0; d < 8; d++)
#pragma unroll
        for (int e = 0; e < 4; e++) oacc[d][e] = 0.f;

    for (int jt = 0; jt < SKV / 64; jt++) {
        __syncthreads();
        // stage K (transposed) and V (direct)
        {
            int r = tid & 63, ch = tid >> 6;  // 4 chunks of 16 d
            const float* kp = g_k + (size_t)(b * SKV + jt * 64 + r) * DM + h * DK + ch * 16;
            const float* vp = g_v + (size_t)(b * SKV + jt * 64 + r) * DM + h * DK + ch * 16;
#pragma unroll
            for (int i = 0; i < 4; i++) {
                float4 v = *(const float4*)(kp + i * 4);
                int d0 = ch * 16 + i * 4;
                Ks[(d0 + 0) * ALDK + r] = f2tf32(v.x);
                Ks[(d0 + 1) * ALDK + r] = f2tf32(v.y);
                Ks[(d0 + 2) * ALDK + r] = f2tf32(v.z);
                Ks[(d0 + 3) * ALDK + r] = f2tf32(v.w);
            }
#pragma unroll
            for (int i = 0; i < 4; i++) {
                float4 v = *(const float4*)(vp + i * 4);
                int d0 = ch * 16 + i * 4;
                uint4 u = make_uint4(f2tf32(v.x), f2tf32(v.y), f2tf32(v.z), f2tf32(v.w));
                *(uint4*)&Vs[r * ALDK + d0] = u;
            }
        }
        __syncthreads();

        // S = Q @ K^T  (warp's 16 rows x 64 kv)
        float sacc[8][4];
#pragma unroll
        for (int n = 0; n < 8; n++)
#pragma unroll
            for (int e = 0; e < 4; e++) sacc[n][e] = 0.f;
#pragma unroll
        for (int ks = 0; ks < 8; ks++) {
            int kb = ks * 8;
            uint32_t qf[4];
            qf[0] = Qs[(kb + tig) * ALDQ + mbase + g];
            qf[1] = Qs[(kb + tig) * ALDQ + mbase + g + 8];
            qf[2] = Qs[(kb + tig + 4) * ALDQ + mbase + g];
            qf[3] = Qs[(kb + tig + 4) * ALDQ + mbase + g + 8];
#pragma unroll
            for (int n = 0; n < 8; n++) {
                uint32_t bf[2];
                bf[0] = Ks[(kb + tig) * ALDK + n * 8 + g];
                bf[1] = Ks[(kb + tig + 4) * ALDK + n * 8 + g];
                mma_tf32(sacc[n], qf, bf);
            }
        }

        // mask + online softmax
        float rmax0 = -1e30f, rmax1 = -1e30f;
#pragma unroll
        for (int n = 0; n < 8; n++) {
            float2 mk = *(const float2*)&mrow[jt * 64 + n * 8 + 2 * tig];
            sacc[n][0] += mk.x; sacc[n][1] += mk.y;
            sacc[n][2] += mk.x; sacc[n][3] += mk.y;
            rmax0 = fmaxf(rmax0, fmaxf(sacc[n][0], sacc[n][1]));
            rmax1 = fmaxf(rmax1, fmaxf(sacc[n][2], sacc[n][3]));
        }
        rmax0 = fmaxf(rmax0, __shfl_xor_sync(0xffffffffu, rmax0, 1));
        rmax0 = fmaxf(rmax0, __shfl_xor_sync(0xffffffffu, rmax0, 2));
        rmax1 = fmaxf(rmax1, __shfl_xor_sync(0xffffffffu, rmax1, 1));
        rmax1 = fmaxf(rmax1, __shfl_xor_sync(0xffffffffu, rmax1, 2));
        float mn0 = fmaxf(m0s, rmax0), mn1 = fmaxf(m1s, rmax1);
        float sc0 = __expf(m0s - mn0), sc1 = __expf(m1s - mn1);
        m0s = mn0; m1s = mn1;
#pragma unroll
        for (int d = 0; d < 8; d++) {
            oacc[d][0] *= sc0; oacc[d][1] *= sc0;
            oacc[d][2] *= sc1; oacc[d][3] *= sc1;
        }
        float rs0 = 0.f, rs1 = 0.f;
#pragma unroll
        for (int n = 0; n < 8; n++) {
            float p0 = __expf(sacc[n][0] - mn0);
            float p1 = __expf(sacc[n][1] - mn0);
            float p2 = __expf(sacc[n][2] - mn1);
            float p3 = __expf(sacc[n][3] - mn1);
            rs0 += p0 + p1;
            rs1 += p2 + p3;
            int c0 = n * 8 + 2 * tig, c1 = c0 + 1;
            Ps[c0 * ALDQ + mbase + g] = f2tf32(p0);
            Ps[c1 * ALDQ + mbase + g] = f2tf32(p1);
            Ps[c0 * ALDQ + mbase + g + 8] = f2tf32(p2);
            Ps[c1 * ALDQ + mbase + g + 8] = f2tf32(p3);
        }
        rs0 += __shfl_xor_sync(0xffffffffu, rs0, 1);
        rs0 += __shfl_xor_sync(0xffffffffu, rs0, 2);
        rs1 += __shfl_xor_sync(0xffffffffu, rs1, 1);
        rs1 += __shfl_xor_sync(0xffffffffu, rs1, 2);
        l0 = l0 * sc0 + rs0;
        l1 = l1 * sc1 + rs1;
        __syncwarp();

        // O += P @ V  (warp reads only its own Ps rows)
#pragma unroll
        for (int ks = 0; ks < 8; ks++) {
            int kb = ks * 8;
            uint32_t pf[4];
            pf[0] = Ps[(kb + tig) * ALDQ + mbase + g];
            pf[1] = Ps[(kb + tig) * ALDQ + mbase + g + 8];
            pf[2] = Ps[(kb + tig + 4) * ALDQ + mbase + g];
            pf[3] = Ps[(kb + tig + 4) * ALDQ + mbase + g + 8];
#pragma unroll
            for (int n = 0; n < 8; n++) {
                uint32_t vf[2];
                vf[0] = Vs[(kb + tig) * ALDK + n * 8 + g];
                vf[1] = Vs[(kb + tig + 4) * ALDK + n * 8 + g];
                mma_tf32(oacc[n], pf, vf);
            }
        }
    }

    // epilogue: divide by l, write ctx
    float inv0 = 1.0f / l0, inv1 = 1.0f / l1;
    int row0 = q0 + mbase + g;
    float* cp0 = g_ctx + (size_t)(b * SQ + row0) * DM + h * DK;
    float* cp1 = g_ctx + (size_t)(b * SQ + row0 + 8) * DM + h * DK;
#pragma unroll
    for (int n = 0; n < 8; n++) {
        int col = n * 8 + 2 * tig;
        *(float2*)&cp0[col] = make_float2(oacc[n][0] * inv0, oacc[n][1] * inv0);
        *(float2*)&cp1[col] = make_float2(oacc[n][2] * inv1, oacc[n][3] * inv1);
    }
}

// ---------------- launch ----------------
extern "C" void kernel_launch(void* const* d_in, const int* in_sizes, int n_in,
                              void* d_out, int out_size) {
    const float* hidden = (const float*)d_in[0];
    const float* kv     = (const float*)d_in[1];
    const float* mask   = (const float*)d_in[2];
    const float* lnw    = (const float*)d_in[3];
    const float* Wq     = (const float*)d_in[4];
    const float* Wk     = (const float*)d_in[5];
    const float* Wv     = (const float*)d_in[6];
    const float* Wo     = (const float*)d_in[7];
    float* out = (float*)d_out;

    float *p_normed, *p_q, *p_k, *p_v, *p_ctx;
    cudaGetSymbolAddress((void**)&p_normed, g_normed);
    cudaGetSymbolAddress((void**)&p_q, g_q);
    cudaGetSymbolAddress((void**)&p_k, g_k);
    cudaGetSymbolAddress((void**)&p_v, g_v);
    cudaGetSymbolAddress((void**)&p_ctx, g_ctx);

    // 1. RMSNorm
    rmsnorm_kernel<<<BB * SQ, 256>>>(hidden, lnw);

    // 2. projections (tf32 tensor-core GEMM)
    dim3 gq(DM / 128, (BB * SQ) / 128);
    dim3 gkv(DM / 128, (BB * SKV) / 128);
    tf32_gemm<false><<<gq, 128>>>(p_normed, Wq, nullptr, p_q, BB * SQ, DM, DM);
    tf32_gemm<false><<<gkv, 128>>>(kv, Wk, nullptr, p_k, BB * SKV, DM, DM);
    tf32_gemm<false><<<gkv, 128>>>(kv, Wv, nullptr, p_v, BB * SKV, DM, DM);

    // 3. flash attention (tf32 tensor-core)
    const int ATTN_SMEM = ATTN_SMEM_U32 * 4;
    cudaFuncSetAttribute(attn_tf32, cudaFuncAttributeMaxDynamicSharedMemorySize, ATTN_SMEM);
    dim3 ga(SQ / 128, NH, BB);
    attn_tf32<<<ga, 256, ATTN_SMEM>>>(mask);

    // 4. output projection + residual
    tf32_gemm<true><<<gq, 128>>>(p_ctx, Wo, hidden, out, BB * SQ, DM, DM);
}